// round 12
// baseline (speedup 1.0000x reference)
#include <cuda_runtime.h>
#include <cuda_fp16.h>
#include <cstdint>

#define DINLINE __device__ __forceinline__

// ----------------------------- config --------------------------------------
static constexpr int B = 16, C = 64;
static constexpr int NSEQ = 65536;
static constexpr int SPLITS = 18;
static constexpr int CHUNK = 64;                 // k elems per smem tile
static constexpr int NCHUNK = NSEQ / CHUNK;      // 1024

// ----------------------------- scratch (no allocs allowed) -----------------
__device__ __align__(16) float g_partA[SPLITS * B * 64 * 64]; // S + X' partials
__device__ __align__(16) float g_partB[SPLITS * B * 64 * 64]; // X'^T partials
__device__ __align__(16) float g_w  [B * 64 * 64];            // compact weights
__device__ __align__(16) int   g_idx[B * 64 * 64];            // compact indices
__device__ __align__(16) int   g_cnt[B * 64];                 // entries per row

// ----------------------------- helpers -------------------------------------
DINLINE uint32_t smem_u32(const void* p) {
    uint32_t a;
    asm("{ .reg .u64 t; cvta.to.shared.u64 t, %1; cvt.u32.u64 %0, t; }"
        : "=r"(a) : "l"(p));
    return a;
}

DINLINE void ldmatrix_x4(uint32_t& r0, uint32_t& r1, uint32_t& r2, uint32_t& r3,
                         uint32_t addr) {
    asm volatile("ldmatrix.sync.aligned.m8n8.x4.shared.b16 {%0,%1,%2,%3}, [%4];"
                 : "=r"(r0), "=r"(r1), "=r"(r2), "=r"(r3) : "r"(addr));
}

DINLINE void mma_16816(float c[4], const uint32_t a[4], uint32_t b0, uint32_t b1) {
    asm volatile(
        "mma.sync.aligned.m16n8k16.row.col.f32.f16.f16.f32 "
        "{%0,%1,%2,%3}, {%4,%5,%6,%7}, {%8,%9}, {%0,%1,%2,%3};"
        : "+f"(c[0]), "+f"(c[1]), "+f"(c[2]), "+f"(c[3])
        : "r"(a[0]), "r"(a[1]), "r"(a[2]), "r"(a[3]), "r"(b0), "r"(b1));
}

DINLINE void bar_named(int id) {
    asm volatile("bar.sync %0, 256;" :: "r"(id) : "memory");
}

// ----------------------------- kernel 1: Gram, warp-specialized -------------
// G = HH^T + HL^T + LH^T (ll dropped).  accS = H H^T, accX = L H^T.
// Warps 0-3: producers (LDG prefetch + fp32->fp16 hi/lo convert + swizzled
// STS). Warps 4-7: consumers (ldmatrix + MMA, 16x64 tile per warp).
// Rendezvous barriers FULL[buf] (bar.sync 1+buf, 256): producer passing
// FULL[i+1] proves the consumer finished chunk i -> buffer i is free.
// partA = S + X (row-major), partB = X transposed (coalesced softmax reads).
__global__ void __launch_bounds__(256, 2) gram_kernel(const float* __restrict__ x) {
    __shared__ __align__(1024) uint8_t smem[2][2][64 * 128];

    const int tid  = threadIdx.x;
    const int wid  = tid >> 5;
    const int lane = tid & 31;
    const int b     = blockIdx.y;
    const int split = blockIdx.x;
    const int c0 = (split * NCHUNK) / SPLITS;
    const int c1 = ((split + 1) * NCHUNK) / SPLITS;
    const int nch = c1 - c0;

    const float* xb = x + (size_t)b * C * NSEQ;

    float accS[8][4], accX[8][4];
#pragma unroll
    for (int n = 0; n < 8; n++)
#pragma unroll
        for (int i = 0; i < 4; i++) { accS[n][i] = 0.0f; accX[n][i] = 0.0f; }

    if (wid < 4) {
        // ================= producer =================
        const int ptid = tid;                    // 0..127
        float4 v[8];
        auto load_chunk = [&](int ci) {
            const int k0 = (c0 + ci) * CHUNK;
#pragma unroll
            for (int u = 0; u < 8; u++) {
                const int f = ptid + u * 128;    // 0..1023
                v[u] = *reinterpret_cast<const float4*>(
                    xb + (size_t)(f >> 4) * NSEQ + (k0 + (f & 15) * 4));
            }
        };
        load_chunk(0);
        for (int i = 0; i < nch; i++) {
            const int buf = i & 1;
#pragma unroll
            for (int u = 0; u < 8; u++) {
                const int f = ptid + u * 128;
                const int row = f >> 4;
                const int kc  = f & 15;
                __half2 h01 = __floats2half2_rn(v[u].x, v[u].y);
                __half2 h23 = __floats2half2_rn(v[u].z, v[u].w);
                __half2 l01 = __floats2half2_rn(v[u].x - __half2float(h01.x),
                                                v[u].y - __half2float(h01.y));
                __half2 l23 = __floats2half2_rn(v[u].z - __half2float(h23.x),
                                                v[u].w - __half2float(h23.y));
                const uint32_t off = (uint32_t)(row * 128
                                     + ((kc >> 1) ^ (row & 7)) * 16 + (kc & 1) * 8);
                uint2 hv, lv;
                hv.x = *reinterpret_cast<uint32_t*>(&h01);
                hv.y = *reinterpret_cast<uint32_t*>(&h23);
                lv.x = *reinterpret_cast<uint32_t*>(&l01);
                lv.y = *reinterpret_cast<uint32_t*>(&l23);
                *reinterpret_cast<uint2*>(&smem[buf][0][off]) = hv;
                *reinterpret_cast<uint2*>(&smem[buf][1][off]) = lv;
            }
            if (i + 1 < nch) load_chunk(i + 1);  // LDGs overlap the barrier wait
            bar_named(1 + buf);                  // FULL[buf] rendezvous
        }
    } else {
        // ================= consumer =================
        const int wm = wid & 3;                  // row slab 16*wm..+15
        const int rowA   = 16 * wm + ((lane >> 3) & 1) * 8 + (lane & 7);
        const int aChAdd = lane >> 4;
        const int rowBl  = ((lane >> 4) << 3) + (lane & 7);
        const int bChAdd = (lane >> 3) & 1;
        auto addr_of = [&](uint32_t base, int row, int chunk) -> uint32_t {
            return base + (uint32_t)(row * 128 + (((chunk) ^ (row & 7)) << 4));
        };
        for (int i = 0; i < nch; i++) {
            const int buf = i & 1;
            bar_named(1 + buf);                  // FULL[buf] rendezvous
            const uint32_t hibase = smem_u32(&smem[buf][0][0]);
            const uint32_t lobase = smem_u32(&smem[buf][1][0]);
#pragma unroll
            for (int s = 0; s < 4; s++) {
                uint32_t ah[4], al[4];
                const int ca = 2 * s + aChAdd;
                ldmatrix_x4(ah[0], ah[1], ah[2], ah[3], addr_of(hibase, rowA, ca));
                ldmatrix_x4(al[0], al[1], al[2], al[3], addr_of(lobase, rowA, ca));
#pragma unroll
                for (int ntp = 0; ntp < 4; ntp++) {
                    const int rb = ntp * 16 + rowBl;
                    const int cb = 2 * s + bChAdd;
                    uint32_t bh0, bh1, bh2, bh3;
                    ldmatrix_x4(bh0, bh1, bh2, bh3, addr_of(hibase, rb, cb));
                    mma_16816(accS[2 * ntp],     ah, bh0, bh1);
                    mma_16816(accS[2 * ntp + 1], ah, bh2, bh3);
                    mma_16816(accX[2 * ntp],     al, bh0, bh1);
                    mma_16816(accX[2 * ntp + 1], al, bh2, bh3);
                }
            }
        }
    }

    __syncthreads();                             // everyone done; smem reusable

    // ---- epilogue: consumers write partA = S + X and stage X ----
    const size_t poff = ((size_t)(split * B + b)) * 64 * 64;
    float* dstA = g_partA + poff;
    float* dstB = g_partB + poff;
    float* st = reinterpret_cast<float*>(&smem[0][0][0]);   // 64x65 staging
    if (wid >= 4) {
        const int wm  = wid & 3;
        const int r0  = 16 * wm + (lane >> 2);
        const int col = 2 * (lane & 3);
#pragma unroll
        for (int nt = 0; nt < 8; nt++) {
            const int cbase = nt * 8 + col;
            float2 alo = make_float2(accS[nt][0] + accX[nt][0],
                                     accS[nt][1] + accX[nt][1]);
            float2 ahi = make_float2(accS[nt][2] + accX[nt][2],
                                     accS[nt][3] + accX[nt][3]);
            *reinterpret_cast<float2*>(&dstA[(size_t)r0 * 64 + cbase])       = alo;
            *reinterpret_cast<float2*>(&dstA[(size_t)(r0 + 8) * 64 + cbase]) = ahi;
            st[r0 * 65 + cbase]           = accX[nt][0];
            st[r0 * 65 + cbase + 1]       = accX[nt][1];
            st[(r0 + 8) * 65 + cbase]     = accX[nt][2];
            st[(r0 + 8) * 65 + cbase + 1] = accX[nt][3];
        }
    }
    __syncthreads();
    // all 256 threads: partB[e][f] = X[f][e], coalesced float4 stores
    {
        const int e  = tid >> 2;            // 0..63
        const int f0 = (tid & 3) * 16;      // 0,16,32,48
#pragma unroll
        for (int g = 0; g < 4; g++) {
            const int f = f0 + g * 4;
            float4 vv;
            vv.x = st[(f + 0) * 65 + e];
            vv.y = st[(f + 1) * 65 + e];
            vv.z = st[(f + 2) * 65 + e];
            vv.w = st[(f + 3) * 65 + e];
            *reinterpret_cast<float4*>(&dstB[(size_t)e * 64 + f]) = vv;
        }
    }
}

// ----------------------------- kernel 2: reduce + softmax -> sparse ---------
// One WARP per (b, c) row. G[c][d] = sum_s partA[c][d] + partB[c][d].
// Pads the list to >= 2 entries (zero weight) for the out kernel fast path.
__global__ void __launch_bounds__(1024) softmax_kernel(const float* __restrict__ gamma) {
    const int b    = blockIdx.y;
    const int wid  = threadIdx.x >> 5;
    const int lane = threadIdx.x & 31;
    const int c    = blockIdx.x * 32 + wid;
    const int d0   = 2 * lane;

    float a0 = 0.0f, a1 = 0.0f;
#pragma unroll
    for (int s = 0; s < SPLITS; s++) {
        const size_t pb = ((size_t)(s * B + b)) * 64 * 64 + (size_t)c * 64 + d0;
        const float2 pa = *reinterpret_cast<const float2*>(&g_partA[pb]);
        const float2 px = *reinterpret_cast<const float2*>(&g_partB[pb]);
        a0 += pa.x + px.x;
        a1 += pa.y + px.y;
    }
    float mn = fminf(a0, a1);
#pragma unroll
    for (int o = 16; o > 0; o >>= 1)
        mn = fminf(mn, __shfl_xor_sync(0xFFFFFFFFu, mn, o));
    float e0 = expf(mn - a0);
    float e1 = expf(mn - a1);
    float Z = e0 + e1;
#pragma unroll
    for (int o = 16; o > 0; o >>= 1)
        Z += __shfl_xor_sync(0xFFFFFFFFu, Z, o);
    const float thr = Z * 1e-11f;
    const float gi = gamma[0] / Z;
    const int k0 = e0 > thr ? 1 : 0;
    const int k1 = e1 > thr ? 1 : 0;
    int incl = k0 + k1;
#pragma unroll
    for (int o = 1; o < 32; o <<= 1) {
        int t = __shfl_up_sync(0xFFFFFFFFu, incl, o);
        if (lane >= o) incl += t;
    }
    int pos = incl - (k0 + k1);
    const size_t base = ((size_t)b * 64 + c) * 64;
    if (k0) { g_idx[base + pos] = d0;     g_w[base + pos] = gi * e0; pos++; }
    if (k1) { g_idx[base + pos] = d0 + 1; g_w[base + pos] = gi * e1; }
    if (lane == 31) {
        g_cnt[b * 64 + c] = incl;
        for (int p = incl; p < 2; p++) { g_idx[base + p] = 0; g_w[base + p] = 0.0f; }
    }
}

// ----------------------------- kernel 3: sparse apply + residual ------------
// out[r,n] = x[r,n] + sum_j w_j * x[d_j, n].  No smem; gather rows are
// warp-uniform coalesced L2 hits. 256-col tiles, metadata hoisted.
__global__ void __launch_bounds__(256) out_kernel(const float* __restrict__ x,
                                                  float* __restrict__ out) {
    const int b   = blockIdx.y;
    const int n   = blockIdx.x * 256 + (threadIdx.x & 31) * 4;
    const int rg  = threadIdx.x >> 5;            // warp id 0..7
    const float* xb = x + (size_t)b * C * NSEQ;
    float* ob = out + (size_t)b * C * NSEQ;

    float w0[8], w1[8];
    int i0[8], i1[8], cnt[8];
#pragma unroll
    for (int k = 0; k < 8; k++) {
        const int r = rg + 8 * k;
        const size_t base = ((size_t)b * 64 + r) * 64;
        cnt[k] = g_cnt[b * 64 + r];
        w0[k] = g_w[base];     i0[k] = g_idx[base];
        w1[k] = g_w[base + 1]; i1[k] = g_idx[base + 1];
    }

#pragma unroll
    for (int k = 0; k < 8; k++) {
        const int r = rg + 8 * k;
        const size_t rowr  = (size_t)r     * NSEQ + n;
        const size_t row0  = (size_t)i0[k] * NSEQ + n;
        const size_t row1  = (size_t)i1[k] * NSEQ + n;
        float4 aA  = *reinterpret_cast<const float4*>(xb + rowr);
        float4 aB  = *reinterpret_cast<const float4*>(xb + rowr + 128);
        float4 s0A = *reinterpret_cast<const float4*>(xb + row0);
        float4 s0B = *reinterpret_cast<const float4*>(xb + row0 + 128);
        float4 s1A = *reinterpret_cast<const float4*>(xb + row1);
        float4 s1B = *reinterpret_cast<const float4*>(xb + row1 + 128);
        const float a0 = w0[k], a1 = w1[k];
        aA.x += a0 * s0A.x + a1 * s1A.x;  aB.x += a0 * s0B.x + a1 * s1B.x;
        aA.y += a0 * s0A.y + a1 * s1A.y;  aB.y += a0 * s0B.y + a1 * s1B.y;
        aA.z += a0 * s0A.z + a1 * s1A.z;  aB.z += a0 * s0B.z + a1 * s1B.z;
        aA.w += a0 * s0A.w + a1 * s1A.w;  aB.w += a0 * s0B.w + a1 * s1B.w;
        if (cnt[k] > 2) {                          // warp-uniform, rare
            const size_t base = ((size_t)b * 64 + r) * 64;
            for (int j = 2; j < cnt[k]; j++) {
                const float w = g_w[base + j];
                const size_t rd = (size_t)g_idx[base + j] * NSEQ + n;
                const float4 sA = *reinterpret_cast<const float4*>(xb + rd);
                const float4 sB = *reinterpret_cast<const float4*>(xb + rd + 128);
                aA.x += w * sA.x; aA.y += w * sA.y; aA.z += w * sA.z; aA.w += w * sA.w;
                aB.x += w * sB.x; aB.y += w * sB.y; aB.z += w * sB.z; aB.w += w * sB.w;
            }
        }
        __stcs(reinterpret_cast<float4*>(ob + rowr), aA);
        __stcs(reinterpret_cast<float4*>(ob + rowr + 128), aB);
    }
}

// ----------------------------- launch ---------------------------------------
extern "C" void kernel_launch(void* const* d_in, const int* in_sizes, int n_in,
                              void* d_out, int out_size) {
    const float* x     = (const float*)d_in[0];
    const float* gamma = (const float*)d_in[1];
    float* out = (float*)d_out;

    gram_kernel<<<dim3(SPLITS, B), 256>>>(x);
    softmax_kernel<<<dim3(2, B), 1024>>>(gamma);
    out_kernel<<<dim3(NSEQ / 256, B), 256>>>(x, out);
}

// round 13
// speedup vs baseline: 1.0255x; 1.0255x over previous
#include <cuda_runtime.h>
#include <cuda_fp16.h>
#include <cstdint>

#define DINLINE __device__ __forceinline__

// ----------------------------- config --------------------------------------
static constexpr int B = 16, C = 64;
static constexpr int NSEQ = 65536;
static constexpr int SPLITS = 18;
static constexpr int CHUNK = 64;                 // k elems per smem tile
static constexpr int NCHUNK = NSEQ / CHUNK;      // 1024

// ----------------------------- scratch (no allocs allowed) -----------------
__device__ __align__(16) float g_partA[SPLITS * B * 64 * 64]; // S + X' partials
__device__ __align__(16) float g_partB[SPLITS * B * 64 * 64]; // X'^T partials
__device__ __align__(16) float g_w  [B * 64 * 64];            // compact weights
__device__ __align__(16) int   g_idx[B * 64 * 64];            // compact indices
__device__ __align__(16) int   g_cnt[B * 64];                 // entries per row

// ----------------------------- helpers -------------------------------------
DINLINE uint32_t smem_u32(const void* p) {
    uint32_t a;
    asm("{ .reg .u64 t; cvta.to.shared.u64 t, %1; cvt.u32.u64 %0, t; }"
        : "=r"(a) : "l"(p));
    return a;
}

DINLINE void ldmatrix_x4(uint32_t& r0, uint32_t& r1, uint32_t& r2, uint32_t& r3,
                         uint32_t addr) {
    asm volatile("ldmatrix.sync.aligned.m8n8.x4.shared.b16 {%0,%1,%2,%3}, [%4];"
                 : "=r"(r0), "=r"(r1), "=r"(r2), "=r"(r3) : "r"(addr));
}

DINLINE void mma_16816(float c[4], const uint32_t a[4], uint32_t b0, uint32_t b1) {
    asm volatile(
        "mma.sync.aligned.m16n8k16.row.col.f32.f16.f16.f32 "
        "{%0,%1,%2,%3}, {%4,%5,%6,%7}, {%8,%9}, {%0,%1,%2,%3};"
        : "+f"(c[0]), "+f"(c[1]), "+f"(c[2]), "+f"(c[3])
        : "r"(a[0]), "r"(a[1]), "r"(a[2]), "r"(a[3]), "r"(b0), "r"(b1));
}

// ----------------------------- kernel 1: Gram via mma.sync ------------------
// R11 tiling (proven fastest), re-pipelined: ONE __syncthreads per chunk.
// Iteration i:  convert+STS chunk i+1 -> buf (i+1)&1   (fma/LSU pipes)
//               LDG chunk i+2 -> v                      (prefetch)
//               ldmatrix+MMA chunk i -> buf i&1         (L1/tensor pipes)
//               __syncthreads
// Different buffers for STS vs MMA reads => no hazard; the barrier both
// publishes the STS and protects buf i&1 from iter i+1's overwrite.
// G = HH^T + HL^T + LH^T (ll dropped).  accS = H H^T, accX = L H^T.
// partA = S + X (row-major), partB = X transposed (coalesced softmax reads).
__global__ void __launch_bounds__(256, 2) gram_kernel(const float* __restrict__ x) {
    __shared__ __align__(1024) uint8_t smem[2][2][64 * 128];

    const int tid  = threadIdx.x;
    const int wid  = tid >> 5;
    const int lane = tid & 31;
    const int wm   = wid & 3;
    const int wn   = wid >> 2;
    const int b     = blockIdx.y;
    const int split = blockIdx.x;
    const int c0 = (split * NCHUNK) / SPLITS;
    const int c1 = ((split + 1) * NCHUNK) / SPLITS;
    const int nch = c1 - c0;

    const float* xb = x + (size_t)b * C * NSEQ;

    float accS[4][4], accX[4][4];
#pragma unroll
    for (int n = 0; n < 4; n++)
#pragma unroll
        for (int i = 0; i < 4; i++) { accS[n][i] = 0.0f; accX[n][i] = 0.0f; }

    const int rowA   = 16 * wm + ((lane >> 3) & 1) * 8 + (lane & 7);
    const int aChAdd = lane >> 4;
    const int rowBl  = ((lane >> 4) << 3) + (lane & 7);
    const int bChAdd = (lane >> 3) & 1;

    float4 v[4];
    auto addr_of = [&](uint32_t base, int row, int chunk) -> uint32_t {
        return base + (uint32_t)(row * 128 + (((chunk) ^ (row & 7)) << 4));
    };
    auto load_chunk = [&](int ci) {
        const int k0 = (c0 + ci) * CHUNK;
#pragma unroll
        for (int u = 0; u < 4; u++) {
            const int f = tid + u * 256;
            v[u] = *reinterpret_cast<const float4*>(
                xb + (size_t)(f >> 4) * NSEQ + (k0 + (f & 15) * 4));
        }
    };
    auto convert_sts = [&](int buf) {
#pragma unroll
        for (int u = 0; u < 4; u++) {
            const int f = tid + u * 256;
            const int row = f >> 4;
            const int kc  = f & 15;
            __half2 h01 = __floats2half2_rn(v[u].x, v[u].y);
            __half2 h23 = __floats2half2_rn(v[u].z, v[u].w);
            __half2 l01 = __floats2half2_rn(v[u].x - __half2float(h01.x),
                                            v[u].y - __half2float(h01.y));
            __half2 l23 = __floats2half2_rn(v[u].z - __half2float(h23.x),
                                            v[u].w - __half2float(h23.y));
            const uint32_t off = (uint32_t)(row * 128 + ((kc >> 1) ^ (row & 7)) * 16
                                            + (kc & 1) * 8);
            uint2 hv, lv;
            hv.x = *reinterpret_cast<uint32_t*>(&h01);
            hv.y = *reinterpret_cast<uint32_t*>(&h23);
            lv.x = *reinterpret_cast<uint32_t*>(&l01);
            lv.y = *reinterpret_cast<uint32_t*>(&l23);
            *reinterpret_cast<uint2*>(&smem[buf][0][off]) = hv;
            *reinterpret_cast<uint2*>(&smem[buf][1][off]) = lv;
        }
    };

    // prologue: chunk 0 staged, chunk 1 in registers
    load_chunk(0);
    convert_sts(0);
    if (nch > 1) load_chunk(1);
    __syncthreads();

    for (int i = 0; i < nch; i++) {
        if (i + 1 < nch) convert_sts((i + 1) & 1);
        if (i + 2 < nch) load_chunk(i + 2);

        const int buf = i & 1;
        const uint32_t hibase = smem_u32(&smem[buf][0][0]);
        const uint32_t lobase = smem_u32(&smem[buf][1][0]);
#pragma unroll
        for (int s = 0; s < 4; s++) {
            uint32_t ah[4], al[4];
            const int ca = 2 * s + aChAdd;
            ldmatrix_x4(ah[0], ah[1], ah[2], ah[3], addr_of(hibase, rowA, ca));
            ldmatrix_x4(al[0], al[1], al[2], al[3], addr_of(lobase, rowA, ca));
#pragma unroll
            for (int ntp = 0; ntp < 2; ntp++) {
                const int rb = wn * 32 + ntp * 16 + rowBl;
                const int cb = 2 * s + bChAdd;
                uint32_t bh0, bh1, bh2, bh3;
                ldmatrix_x4(bh0, bh1, bh2, bh3, addr_of(hibase, rb, cb));
                mma_16816(accS[2 * ntp],     ah, bh0, bh1);
                mma_16816(accS[2 * ntp + 1], ah, bh2, bh3);
                mma_16816(accX[2 * ntp],     al, bh0, bh1);
                mma_16816(accX[2 * ntp + 1], al, bh2, bh3);
            }
        }
        __syncthreads();
    }

    // ---- epilogue: partA = S + X' (coalesced); partB = X'^T via smem ----
    const size_t poff = ((size_t)(split * B + b)) * 64 * 64;
    float* dstA = g_partA + poff;
    float* dstB = g_partB + poff;
    const int r0  = 16 * wm + (lane >> 2);
    const int col = 2 * (lane & 3);
    float* st = reinterpret_cast<float*>(&smem[0][0][0]);   // 64x65 staging
#pragma unroll
    for (int nt = 0; nt < 4; nt++) {
        const int cbase = wn * 32 + nt * 8 + col;
        float2 alo = make_float2(accS[nt][0] + accX[nt][0], accS[nt][1] + accX[nt][1]);
        float2 ahi = make_float2(accS[nt][2] + accX[nt][2], accS[nt][3] + accX[nt][3]);
        *reinterpret_cast<float2*>(&dstA[(size_t)r0 * 64 + cbase])       = alo;
        *reinterpret_cast<float2*>(&dstA[(size_t)(r0 + 8) * 64 + cbase]) = ahi;
        st[r0 * 65 + cbase]           = accX[nt][0];
        st[r0 * 65 + cbase + 1]       = accX[nt][1];
        st[(r0 + 8) * 65 + cbase]     = accX[nt][2];
        st[(r0 + 8) * 65 + cbase + 1] = accX[nt][3];
    }
    __syncthreads();
    {
        const int e  = tid >> 2;            // 0..63
        const int f0 = (tid & 3) * 16;      // 0,16,32,48
#pragma unroll
        for (int g = 0; g < 4; g++) {
            const int f = f0 + g * 4;
            float4 vv;
            vv.x = st[(f + 0) * 65 + e];
            vv.y = st[(f + 1) * 65 + e];
            vv.z = st[(f + 2) * 65 + e];
            vv.w = st[(f + 3) * 65 + e];
            *reinterpret_cast<float4*>(&dstB[(size_t)e * 64 + f]) = vv;
        }
    }
}

// ----------------------------- kernel 2: reduce + softmax -> sparse ---------
// One WARP per (b, c) row. G[c][d] = sum_s partA[c][d] + partB[c][d].
// Pads the list to >= 2 entries (zero weight) for the out kernel fast path.
__global__ void __launch_bounds__(1024) softmax_kernel(const float* __restrict__ gamma) {
    const int b    = blockIdx.y;
    const int wid  = threadIdx.x >> 5;
    const int lane = threadIdx.x & 31;
    const int c    = blockIdx.x * 32 + wid;
    const int d0   = 2 * lane;

    float a0 = 0.0f, a1 = 0.0f;
#pragma unroll
    for (int s = 0; s < SPLITS; s++) {
        const size_t pb = ((size_t)(s * B + b)) * 64 * 64 + (size_t)c * 64 + d0;
        const float2 pa = *reinterpret_cast<const float2*>(&g_partA[pb]);
        const float2 px = *reinterpret_cast<const float2*>(&g_partB[pb]);
        a0 += pa.x + px.x;
        a1 += pa.y + px.y;
    }
    float mn = fminf(a0, a1);
#pragma unroll
    for (int o = 16; o > 0; o >>= 1)
        mn = fminf(mn, __shfl_xor_sync(0xFFFFFFFFu, mn, o));
    float e0 = expf(mn - a0);
    float e1 = expf(mn - a1);
    float Z = e0 + e1;
#pragma unroll
    for (int o = 16; o > 0; o >>= 1)
        Z += __shfl_xor_sync(0xFFFFFFFFu, Z, o);
    const float thr = Z * 1e-11f;
    const float gi = gamma[0] / Z;
    const int k0 = e0 > thr ? 1 : 0;
    const int k1 = e1 > thr ? 1 : 0;
    int incl = k0 + k1;
#pragma unroll
    for (int o = 1; o < 32; o <<= 1) {
        int t = __shfl_up_sync(0xFFFFFFFFu, incl, o);
        if (lane >= o) incl += t;
    }
    int pos = incl - (k0 + k1);
    const size_t base = ((size_t)b * 64 + c) * 64;
    if (k0) { g_idx[base + pos] = d0;     g_w[base + pos] = gi * e0; pos++; }
    if (k1) { g_idx[base + pos] = d0 + 1; g_w[base + pos] = gi * e1; }
    if (lane == 31) {
        g_cnt[b * 64 + c] = incl;
        for (int p = incl; p < 2; p++) { g_idx[base + p] = 0; g_w[base + p] = 0.0f; }
    }
}

// ----------------------------- kernel 3: sparse apply + residual ------------
// out[r,n] = x[r,n] + sum_j w_j * x[d_j, n].  No smem; gather rows are
// warp-uniform coalesced L2 hits. 256-col tiles, metadata hoisted.
__global__ void __launch_bounds__(256) out_kernel(const float* __restrict__ x,
                                                  float* __restrict__ out) {
    const int b   = blockIdx.y;
    const int n   = blockIdx.x * 256 + (threadIdx.x & 31) * 4;
    const int rg  = threadIdx.x >> 5;            // warp id 0..7
    const float* xb = x + (size_t)b * C * NSEQ;
    float* ob = out + (size_t)b * C * NSEQ;

    float w0[8], w1[8];
    int i0[8], i1[8], cnt[8];
#pragma unroll
    for (int k = 0; k < 8; k++) {
        const int r = rg + 8 * k;
        const size_t base = ((size_t)b * 64 + r) * 64;
        cnt[k] = g_cnt[b * 64 + r];
        w0[k] = g_w[base];     i0[k] = g_idx[base];
        w1[k] = g_w[base + 1]; i1[k] = g_idx[base + 1];
    }

#pragma unroll
    for (int k = 0; k < 8; k++) {
        const int r = rg + 8 * k;
        const size_t rowr  = (size_t)r     * NSEQ + n;
        const size_t row0  = (size_t)i0[k] * NSEQ + n;
        const size_t row1  = (size_t)i1[k] * NSEQ + n;
        float4 aA  = *reinterpret_cast<const float4*>(xb + rowr);
        float4 aB  = *reinterpret_cast<const float4*>(xb + rowr + 128);
        float4 s0A = *reinterpret_cast<const float4*>(xb + row0);
        float4 s0B = *reinterpret_cast<const float4*>(xb + row0 + 128);
        float4 s1A = *reinterpret_cast<const float4*>(xb + row1);
        float4 s1B = *reinterpret_cast<const float4*>(xb + row1 + 128);
        const float a0 = w0[k], a1 = w1[k];
        aA.x += a0 * s0A.x + a1 * s1A.x;  aB.x += a0 * s0B.x + a1 * s1B.x;
        aA.y += a0 * s0A.y + a1 * s1A.y;  aB.y += a0 * s0B.y + a1 * s1B.y;
        aA.z += a0 * s0A.z + a1 * s1A.z;  aB.z += a0 * s0B.z + a1 * s1B.z;
        aA.w += a0 * s0A.w + a1 * s1A.w;  aB.w += a0 * s0B.w + a1 * s1B.w;
        if (cnt[k] > 2) {                          // warp-uniform, rare
            const size_t base = ((size_t)b * 64 + r) * 64;
            for (int j = 2; j < cnt[k]; j++) {
                const float w = g_w[base + j];
                const size_t rd = (size_t)g_idx[base + j] * NSEQ + n;
                const float4 sA = *reinterpret_cast<const float4*>(xb + rd);
                const float4 sB = *reinterpret_cast<const float4*>(xb + rd + 128);
                aA.x += w * sA.x; aA.y += w * sA.y; aA.z += w * sA.z; aA.w += w * sA.w;
                aB.x += w * sB.x; aB.y += w * sB.y; aB.z += w * sB.z; aB.w += w * sB.w;
            }
        }
        __stcs(reinterpret_cast<float4*>(ob + rowr), aA);
        __stcs(reinterpret_cast<float4*>(ob + rowr + 128), aB);
    }
}

// ----------------------------- launch ---------------------------------------
extern "C" void kernel_launch(void* const* d_in, const int* in_sizes, int n_in,
                              void* d_out, int out_size) {
    const float* x     = (const float*)d_in[0];
    const float* gamma = (const float*)d_in[1];
    float* out = (float*)d_out;

    gram_kernel<<<dim3(SPLITS, B), 256>>>(x);
    softmax_kernel<<<dim3(2, B), 1024>>>(gamma);
    out_kernel<<<dim3(NSEQ / 256, B), 256>>>(x, out);
}

// round 14
// speedup vs baseline: 1.0279x; 1.0023x over previous
#include <cuda_runtime.h>
#include <cuda_fp16.h>
#include <cstdint>

#define DINLINE __device__ __forceinline__

// ----------------------------- config --------------------------------------
static constexpr int B = 16, C = 64;
static constexpr int NSEQ = 65536;
static constexpr int SPLITS = 18;
static constexpr int CHUNK = 64;                 // k elems per smem tile
static constexpr int NCHUNK = NSEQ / CHUNK;      // 1024

// gram dynamic smem layout (80 KB):
//   [0, 32K):  fp16 bufs  buf(2) x hilo(2) x 8KB
//   [32K,80K): fp32 stages 3 x 16KB
static constexpr int FP16_BUF_BYTES = 64 * 128;          // 8 KB
static constexpr int STAGE_OFF      = 4 * FP16_BUF_BYTES; // 32 KB
static constexpr int STAGE_BYTES    = 64 * 256;           // 16 KB
static constexpr int GRAM_DSMEM     = STAGE_OFF + 3 * STAGE_BYTES; // 80 KB

// ----------------------------- scratch (no allocs allowed) -----------------
__device__ __align__(16) float g_partA[SPLITS * B * 64 * 64]; // S + X' partials
__device__ __align__(16) float g_partB[SPLITS * B * 64 * 64]; // X'^T partials
__device__ __align__(16) float g_w  [B * 64 * 64];            // compact weights
__device__ __align__(16) int   g_idx[B * 64 * 64];            // compact indices
__device__ __align__(16) int   g_cnt[B * 64];                 // entries per row

// ----------------------------- helpers -------------------------------------
DINLINE uint32_t smem_u32(const void* p) {
    uint32_t a;
    asm("{ .reg .u64 t; cvta.to.shared.u64 t, %1; cvt.u32.u64 %0, t; }"
        : "=r"(a) : "l"(p));
    return a;
}

DINLINE void ldmatrix_x4(uint32_t& r0, uint32_t& r1, uint32_t& r2, uint32_t& r3,
                         uint32_t addr) {
    asm volatile("ldmatrix.sync.aligned.m8n8.x4.shared.b16 {%0,%1,%2,%3}, [%4];"
                 : "=r"(r0), "=r"(r1), "=r"(r2), "=r"(r3) : "r"(addr));
}

DINLINE void mma_16816(float c[4], const uint32_t a[4], uint32_t b0, uint32_t b1) {
    asm volatile(
        "mma.sync.aligned.m16n8k16.row.col.f32.f16.f16.f32 "
        "{%0,%1,%2,%3}, {%4,%5,%6,%7}, {%8,%9}, {%0,%1,%2,%3};"
        : "+f"(c[0]), "+f"(c[1]), "+f"(c[2]), "+f"(c[3])
        : "r"(a[0]), "r"(a[1]), "r"(a[2]), "r"(a[3]), "r"(b0), "r"(b1));
}

DINLINE void cp_async16(uint32_t smem_addr, const void* gptr) {
    asm volatile("cp.async.cg.shared.global [%0], [%1], 16;"
                 :: "r"(smem_addr), "l"(gptr) : "memory");
}
DINLINE void cp_commit() { asm volatile("cp.async.commit_group;" ::: "memory"); }
template <int N>
DINLINE void cp_wait() { asm volatile("cp.async.wait_group %0;" :: "n"(N) : "memory"); }

// ----------------------------- kernel 1: Gram via mma.sync ------------------
// R13 tiling & accumulation order (bit-identical result); the DRAM feed is
// now a depth-2 cp.async pipeline into fp32 smem stages (no register
// prefetch): chunk i computes while chunks i+2 and i+3 stream in.
// Each thread converts exactly the bytes it cp.async'd (same f mapping), so
// per-thread wait_group gives visibility without an extra barrier.
// G = HH^T + HL^T + LH^T (ll dropped).  accS = H H^T, accX = L H^T.
// partA = S + X (row-major), partB = X transposed (coalesced softmax reads).
__global__ void __launch_bounds__(256, 2) gram_kernel(const float* __restrict__ x) {
    extern __shared__ __align__(1024) uint8_t dsm[];

    const int tid  = threadIdx.x;
    const int wid  = tid >> 5;
    const int lane = tid & 31;
    const int wm   = wid & 3;
    const int wn   = wid >> 2;
    const int b     = blockIdx.y;
    const int split = blockIdx.x;
    const int c0 = (split * NCHUNK) / SPLITS;
    const int c1 = ((split + 1) * NCHUNK) / SPLITS;
    const int nch = c1 - c0;                       // 56..57 (>= 3 always)

    const float* xb = x + (size_t)b * C * NSEQ;
    const uint32_t dbase = smem_u32(dsm);

    float accS[4][4], accX[4][4];
#pragma unroll
    for (int n = 0; n < 4; n++)
#pragma unroll
        for (int i = 0; i < 4; i++) { accS[n][i] = 0.0f; accX[n][i] = 0.0f; }

    const int rowA   = 16 * wm + ((lane >> 3) & 1) * 8 + (lane & 7);
    const int aChAdd = lane >> 4;
    const int rowBl  = ((lane >> 4) << 3) + (lane & 7);
    const int bChAdd = (lane >> 3) & 1;

    auto addr_of = [&](uint32_t base, int row, int chunk) -> uint32_t {
        return base + (uint32_t)(row * 128 + (((chunk) ^ (row & 7)) << 4));
    };
    // issue one chunk's 4 cp.asyncs (16B each) into stage ci%3, then commit
    auto cp_chunk = [&](int ci) {
        const int k0 = (c0 + ci) * CHUNK;
        const uint32_t sb = dbase + STAGE_OFF + (ci % 3) * STAGE_BYTES;
#pragma unroll
        for (int u = 0; u < 4; u++) {
            const int f = tid + u * 256;           // 0..1023
            cp_async16(sb + (uint32_t)f * 16,
                       xb + (size_t)(f >> 4) * NSEQ + (k0 + (f & 15) * 4));
        }
        cp_commit();
    };
    // convert chunk ci (this thread's own staged bytes) -> fp16 buf ci&1
    auto convert_sts = [&](int ci) {
        const float* sg = reinterpret_cast<const float*>(
            dsm + STAGE_OFF + (ci % 3) * STAGE_BYTES);
        uint8_t* hb = dsm + ((ci & 1) * 2 + 0) * FP16_BUF_BYTES;
        uint8_t* lb = dsm + ((ci & 1) * 2 + 1) * FP16_BUF_BYTES;
#pragma unroll
        for (int u = 0; u < 4; u++) {
            const int f = tid + u * 256;
            const int row = f >> 4;
            const int kc  = f & 15;
            const float4 vv = *reinterpret_cast<const float4*>(sg + f * 4);
            __half2 h01 = __floats2half2_rn(vv.x, vv.y);
            __half2 h23 = __floats2half2_rn(vv.z, vv.w);
            __half2 l01 = __floats2half2_rn(vv.x - __half2float(h01.x),
                                            vv.y - __half2float(h01.y));
            __half2 l23 = __floats2half2_rn(vv.z - __half2float(h23.x),
                                            vv.w - __half2float(h23.y));
            const uint32_t off = (uint32_t)(row * 128 + ((kc >> 1) ^ (row & 7)) * 16
                                            + (kc & 1) * 8);
            uint2 hv, lv;
            hv.x = *reinterpret_cast<uint32_t*>(&h01);
            hv.y = *reinterpret_cast<uint32_t*>(&h23);
            lv.x = *reinterpret_cast<uint32_t*>(&l01);
            lv.y = *reinterpret_cast<uint32_t*>(&l23);
            *reinterpret_cast<uint2*>(hb + off) = hv;
            *reinterpret_cast<uint2*>(lb + off) = lv;
        }
    };

    // prologue: stream chunks 0..2, convert chunk 0
    cp_chunk(0);
    cp_chunk(1);
    cp_chunk(2);
    cp_wait<2>();                                  // chunk 0 landed (own bytes)
    convert_sts(0);
    __syncthreads();                               // publish fp16 buf 0

    for (int i = 0; i < nch; i++) {
        if (i + 1 < nch) {
            if (i + 2 < nch) cp_wait<1>(); else cp_wait<0>();
            convert_sts(i + 1);                    // writes buf (i+1)&1
        }
        if (i + 3 < nch) cp_chunk(i + 3);          // reuses stage i%3's slot...
                                                   // (i+3)%3 == i%3: converted
                                                   // by this thread at iter i-1
        const int buf = i & 1;
        const uint32_t hibase = dbase + (buf * 2 + 0) * FP16_BUF_BYTES;
        const uint32_t lobase = dbase + (buf * 2 + 1) * FP16_BUF_BYTES;
#pragma unroll
        for (int s = 0; s < 4; s++) {
            uint32_t ah[4], al[4];
            const int ca = 2 * s + aChAdd;
            ldmatrix_x4(ah[0], ah[1], ah[2], ah[3], addr_of(hibase, rowA, ca));
            ldmatrix_x4(al[0], al[1], al[2], al[3], addr_of(lobase, rowA, ca));
#pragma unroll
            for (int ntp = 0; ntp < 2; ntp++) {
                const int rb = wn * 32 + ntp * 16 + rowBl;
                const int cb = 2 * s + bChAdd;
                uint32_t bh0, bh1, bh2, bh3;
                ldmatrix_x4(bh0, bh1, bh2, bh3, addr_of(hibase, rb, cb));
                mma_16816(accS[2 * ntp],     ah, bh0, bh1);
                mma_16816(accS[2 * ntp + 1], ah, bh2, bh3);
                mma_16816(accX[2 * ntp],     al, bh0, bh1);
                mma_16816(accX[2 * ntp + 1], al, bh2, bh3);
            }
        }
        __syncthreads();   // publishes buf (i+1)&1 STS; frees buf i&1 for reuse
    }

    // ---- epilogue: partA = S + X' (coalesced); partB = X'^T via smem ----
    const size_t poff = ((size_t)(split * B + b)) * 64 * 64;
    float* dstA = g_partA + poff;
    float* dstB = g_partB + poff;
    const int r0  = 16 * wm + (lane >> 2);
    const int col = 2 * (lane & 3);
    float* st = reinterpret_cast<float*>(dsm);     // 64x65 staging
#pragma unroll
    for (int nt = 0; nt < 4; nt++) {
        const int cbase = wn * 32 + nt * 8 + col;
        float2 alo = make_float2(accS[nt][0] + accX[nt][0], accS[nt][1] + accX[nt][1]);
        float2 ahi = make_float2(accS[nt][2] + accX[nt][2], accS[nt][3] + accX[nt][3]);
        *reinterpret_cast<float2*>(&dstA[(size_t)r0 * 64 + cbase])       = alo;
        *reinterpret_cast<float2*>(&dstA[(size_t)(r0 + 8) * 64 + cbase]) = ahi;
        st[r0 * 65 + cbase]           = accX[nt][0];
        st[r0 * 65 + cbase + 1]       = accX[nt][1];
        st[(r0 + 8) * 65 + cbase]     = accX[nt][2];
        st[(r0 + 8) * 65 + cbase + 1] = accX[nt][3];
    }
    __syncthreads();
    {
        const int e  = tid >> 2;            // 0..63
        const int f0 = (tid & 3) * 16;      // 0,16,32,48
#pragma unroll
        for (int g = 0; g < 4; g++) {
            const int f = f0 + g * 4;
            float4 vv;
            vv.x = st[(f + 0) * 65 + e];
            vv.y = st[(f + 1) * 65 + e];
            vv.z = st[(f + 2) * 65 + e];
            vv.w = st[(f + 3) * 65 + e];
            *reinterpret_cast<float4*>(&dstB[(size_t)e * 64 + f]) = vv;
        }
    }
}

// ----------------------------- kernel 2: reduce + softmax -> sparse ---------
// One WARP per (b, c) row. G[c][d] = sum_s partA[c][d] + partB[c][d].
// Pads the list to >= 2 entries (zero weight) for the out kernel fast path.
__global__ void __launch_bounds__(1024) softmax_kernel(const float* __restrict__ gamma) {
    const int b    = blockIdx.y;
    const int wid  = threadIdx.x >> 5;
    const int lane = threadIdx.x & 31;
    const int c    = blockIdx.x * 32 + wid;
    const int d0   = 2 * lane;

    float a0 = 0.0f, a1 = 0.0f;
#pragma unroll
    for (int s = 0; s < SPLITS; s++) {
        const size_t pb = ((size_t)(s * B + b)) * 64 * 64 + (size_t)c * 64 + d0;
        const float2 pa = *reinterpret_cast<const float2*>(&g_partA[pb]);
        const float2 px = *reinterpret_cast<const float2*>(&g_partB[pb]);
        a0 += pa.x + px.x;
        a1 += pa.y + px.y;
    }
    float mn = fminf(a0, a1);
#pragma unroll
    for (int o = 16; o > 0; o >>= 1)
        mn = fminf(mn, __shfl_xor_sync(0xFFFFFFFFu, mn, o));
    float e0 = expf(mn - a0);
    float e1 = expf(mn - a1);
    float Z = e0 + e1;
#pragma unroll
    for (int o = 16; o > 0; o >>= 1)
        Z += __shfl_xor_sync(0xFFFFFFFFu, Z, o);
    const float thr = Z * 1e-11f;
    const float gi = gamma[0] / Z;
    const int k0 = e0 > thr ? 1 : 0;
    const int k1 = e1 > thr ? 1 : 0;
    int incl = k0 + k1;
#pragma unroll
    for (int o = 1; o < 32; o <<= 1) {
        int t = __shfl_up_sync(0xFFFFFFFFu, incl, o);
        if (lane >= o) incl += t;
    }
    int pos = incl - (k0 + k1);
    const size_t base = ((size_t)b * 64 + c) * 64;
    if (k0) { g_idx[base + pos] = d0;     g_w[base + pos] = gi * e0; pos++; }
    if (k1) { g_idx[base + pos] = d0 + 1; g_w[base + pos] = gi * e1; }
    if (lane == 31) {
        g_cnt[b * 64 + c] = incl;
        for (int p = incl; p < 2; p++) { g_idx[base + p] = 0; g_w[base + p] = 0.0f; }
    }
}

// ----------------------------- kernel 3: sparse apply + residual ------------
// out[r,n] = x[r,n] + sum_j w_j * x[d_j, n].  No smem; gather rows are
// warp-uniform coalesced L2 hits. 256-col tiles, metadata hoisted.
__global__ void __launch_bounds__(256) out_kernel(const float* __restrict__ x,
                                                  float* __restrict__ out) {
    const int b   = blockIdx.y;
    const int n   = blockIdx.x * 256 + (threadIdx.x & 31) * 4;
    const int rg  = threadIdx.x >> 5;            // warp id 0..7
    const float* xb = x + (size_t)b * C * NSEQ;
    float* ob = out + (size_t)b * C * NSEQ;

    float w0[8], w1[8];
    int i0[8], i1[8], cnt[8];
#pragma unroll
    for (int k = 0; k < 8; k++) {
        const int r = rg + 8 * k;
        const size_t base = ((size_t)b * 64 + r) * 64;
        cnt[k] = g_cnt[b * 64 + r];
        w0[k] = g_w[base];     i0[k] = g_idx[base];
        w1[k] = g_w[base + 1]; i1[k] = g_idx[base + 1];
    }

#pragma unroll
    for (int k = 0; k < 8; k++) {
        const int r = rg + 8 * k;
        const size_t rowr  = (size_t)r     * NSEQ + n;
        const size_t row0  = (size_t)i0[k] * NSEQ + n;
        const size_t row1  = (size_t)i1[k] * NSEQ + n;
        float4 aA  = *reinterpret_cast<const float4*>(xb + rowr);
        float4 aB  = *reinterpret_cast<const float4*>(xb + rowr + 128);
        float4 s0A = *reinterpret_cast<const float4*>(xb + row0);
        float4 s0B = *reinterpret_cast<const float4*>(xb + row0 + 128);
        float4 s1A = *reinterpret_cast<const float4*>(xb + row1);
        float4 s1B = *reinterpret_cast<const float4*>(xb + row1 + 128);
        const float a0 = w0[k], a1 = w1[k];
        aA.x += a0 * s0A.x + a1 * s1A.x;  aB.x += a0 * s0B.x + a1 * s1B.x;
        aA.y += a0 * s0A.y + a1 * s1A.y;  aB.y += a0 * s0B.y + a1 * s1B.y;
        aA.z += a0 * s0A.z + a1 * s1A.z;  aB.z += a0 * s0B.z + a1 * s1B.z;
        aA.w += a0 * s0A.w + a1 * s1A.w;  aB.w += a0 * s0B.w + a1 * s1B.w;
        if (cnt[k] > 2) {                          // warp-uniform, rare
            const size_t base = ((size_t)b * 64 + r) * 64;
            for (int j = 2; j < cnt[k]; j++) {
                const float w = g_w[base + j];
                const size_t rd = (size_t)g_idx[base + j] * NSEQ + n;
                const float4 sA = *reinterpret_cast<const float4*>(xb + rd);
                const float4 sB = *reinterpret_cast<const float4*>(xb + rd + 128);
                aA.x += w * sA.x; aA.y += w * sA.y; aA.z += w * sA.z; aA.w += w * sA.w;
                aB.x += w * sB.x; aB.y += w * sB.y; aB.z += w * sB.z; aB.w += w * sB.w;
            }
        }
        __stcs(reinterpret_cast<float4*>(ob + rowr), aA);
        __stcs(reinterpret_cast<float4*>(ob + rowr + 128), aB);
    }
}

// ----------------------------- launch ---------------------------------------
extern "C" void kernel_launch(void* const* d_in, const int* in_sizes, int n_in,
                              void* d_out, int out_size) {
    const float* x     = (const float*)d_in[0];
    const float* gamma = (const float*)d_in[1];
    float* out = (float*)d_out;

    cudaFuncSetAttribute(gram_kernel, cudaFuncAttributeMaxDynamicSharedMemorySize,
                         GRAM_DSMEM);

    gram_kernel<<<dim3(SPLITS, B), 256, GRAM_DSMEM>>>(x);
    softmax_kernel<<<dim3(2, B), 1024>>>(gamma);
    out_kernel<<<dim3(NSEQ / 256, B), 256>>>(x, out);
}